// round 5
// baseline (speedup 1.0000x reference)
#include <cuda_runtime.h>
#include <math.h>

#define ADAPTERS 40
#define CAPS 3
#define CLASS_DIM 200
#define IN_CH 600
#define BATCH 256
#define DHID 768

// Scratch (static device arrays -- no allocation at runtime)
__device__ float g_xT[ADAPTERS * IN_CH * BATCH];          // [k][c][b]
__device__ float g_P[CAPS * ADAPTERS * BATCH * CLASS_DIM]; // [n][k][b][d], zero for k>t
__device__ float g_V[CAPS * BATCH * CLASS_DIM];            // [n][b][d] flat

// ---------------------------------------------------------------------------
// f32x2 packed-FMA helpers (sm_103a FFMA2 path; ptxas won't emit from C++)
// ---------------------------------------------------------------------------
__device__ __forceinline__ unsigned long long pk2(float lo, float hi) {
    unsigned long long r;
    asm("mov.b64 %0, {%1, %2};" : "=l"(r) : "f"(lo), "f"(hi));
    return r;
}
__device__ __forceinline__ void ffma2(unsigned long long& c, unsigned long long a, unsigned long long b) {
    asm("fma.rn.f32x2 %0, %1, %2, %0;" : "+l"(c) : "l"(a), "l"(b));
}
__device__ __forceinline__ void unpk2(unsigned long long v, float& lo, float& hi) {
    asm("mov.b64 {%0, %1}, %2;" : "=f"(lo), "=f"(hi) : "l"(v));
}

// ---------------------------------------------------------------------------
// Kernel 0: transpose x (b,k,c) -> xT (k,c,b); only k<=t slices are consumed
// ---------------------------------------------------------------------------
__global__ void k_transpose(const float* __restrict__ x, const int* __restrict__ tptr) {
    int k = blockIdx.x;
    if (k > *tptr) return;
    __shared__ float tile[32][33];
    int c0 = blockIdx.y * 32;
    int b0 = blockIdx.z * 32;
    int tx = threadIdx.x, ty = threadIdx.y;  // (32, 8)
#pragma unroll
    for (int i = 0; i < 4; i++) {
        int b = b0 + ty + i * 8;
        int c = c0 + tx;
        float v = 0.f;
        if (c < IN_CH) v = x[((size_t)b * ADAPTERS + k) * IN_CH + c];
        tile[ty + i * 8][tx] = v;
    }
    __syncthreads();
#pragma unroll
    for (int i = 0; i < 4; i++) {
        int c = c0 + ty + i * 8;
        int b = b0 + tx;
        if (c < IN_CH) g_xT[((size_t)k * IN_CH + c) * BATCH + b] = tile[tx][ty + i * 8];
    }
}

// ---------------------------------------------------------------------------
// Kernel 1: priors GEMM, v3: 8x16 thread tiles so the FMA pipe (not the smem
// crossbar) is binding. Per kk: 6 LDS.128 (24 SM-cyc of crossbar) feeds
// 64 FFMA2 (32 SM-cyc of FMA capacity). BM=128, BN=128, BK=8, 128 threads.
// For each (k,n):  C[256x200] = A[256x600] B[600x200]
// ---------------------------------------------------------------------------
#define BM 128
#define BN 128
#define BKK 8
#define NTILES (IN_CH / BKK)

__global__ __launch_bounds__(128) void k_gemm(const float* __restrict__ rw,
                                              const int* __restrict__ tptr) {
    int t = *tptr;
    int kn = blockIdx.z;
    int k = kn / 3, n = kn % 3;
    if (k > t) return;  // only k<=t contribute (softmax underflow), uniform exit

    int b0 = blockIdx.x * BM;
    int d0 = blockIdx.y * BN;

    __shared__ float As[BKK][BM];
    __shared__ float Bs[BKK][BN];

    int tid = threadIdx.x;
    int tn = tid & 7;        // 0..7  -> n0 = tn*16
    int tm = tid >> 3;       // 0..15 -> m0 = tm*8
    int m0 = tm * 8;
    int n0 = tn * 16;

    unsigned long long acc[8][8];
#pragma unroll
    for (int i = 0; i < 8; i++)
#pragma unroll
        for (int j = 0; j < 8; j++) acc[i][j] = 0ull;

    // Tile-load mapping: 8 rows x 128 cols, 16 threads/row, 8 floats each
    int lrow = tid >> 4;        // 0..7
    int lcol = (tid & 15) * 8;  // 0..120

    const float* Aptr = g_xT + (size_t)k * IN_CH * BATCH + (size_t)lrow * BATCH + b0 + lcol;
    const float* Bptr = rw + (size_t)(k * 3 + n) * IN_CH * CLASS_DIM + (size_t)lrow * CLASS_DIM + d0 + lcol;
    bool bval0 = (d0 + lcol) < CLASS_DIM;       // float4 granularity (200 % 4 == 0)
    bool bval1 = (d0 + lcol + 4) < CLASS_DIM;

    // Prologue: load tile 0
    float4 a0 = *reinterpret_cast<const float4*>(Aptr);
    float4 a1 = *reinterpret_cast<const float4*>(Aptr + 4);
    float4 bb0 = make_float4(0.f, 0.f, 0.f, 0.f), bb1 = bb0;
    if (bval0) bb0 = *reinterpret_cast<const float4*>(Bptr);
    if (bval1) bb1 = *reinterpret_cast<const float4*>(Bptr + 4);
    Aptr += BKK * BATCH;
    Bptr += BKK * CLASS_DIM;

    for (int ct = 0; ct < NTILES; ct++) {
        __syncthreads();
        *reinterpret_cast<float4*>(&As[lrow][lcol]) = a0;
        *reinterpret_cast<float4*>(&As[lrow][lcol + 4]) = a1;
        *reinterpret_cast<float4*>(&Bs[lrow][lcol]) = bb0;
        *reinterpret_cast<float4*>(&Bs[lrow][lcol + 4]) = bb1;
        __syncthreads();

        // Prefetch next tile's global loads: latency hides under compute below
        if (ct + 1 < NTILES) {
            a0 = *reinterpret_cast<const float4*>(Aptr);
            a1 = *reinterpret_cast<const float4*>(Aptr + 4);
            if (bval0) bb0 = *reinterpret_cast<const float4*>(Bptr);
            if (bval1) bb1 = *reinterpret_cast<const float4*>(Bptr + 4);
            Aptr += BKK * BATCH;
            Bptr += BKK * CLASS_DIM;
        }

#pragma unroll
        for (int kk = 0; kk < BKK; kk++) {
            const float4 av0 = *reinterpret_cast<const float4*>(&As[kk][m0]);
            const float4 av1 = *reinterpret_cast<const float4*>(&As[kk][m0 + 4]);
            const float4 bv0 = *reinterpret_cast<const float4*>(&Bs[kk][n0]);
            const float4 bv1 = *reinterpret_cast<const float4*>(&Bs[kk][n0 + 4]);
            const float4 bv2 = *reinterpret_cast<const float4*>(&Bs[kk][n0 + 8]);
            const float4 bv3 = *reinterpret_cast<const float4*>(&Bs[kk][n0 + 12]);
            unsigned long long bp[8];
            bp[0] = pk2(bv0.x, bv0.y);
            bp[1] = pk2(bv0.z, bv0.w);
            bp[2] = pk2(bv1.x, bv1.y);
            bp[3] = pk2(bv1.z, bv1.w);
            bp[4] = pk2(bv2.x, bv2.y);
            bp[5] = pk2(bv2.z, bv2.w);
            bp[6] = pk2(bv3.x, bv3.y);
            bp[7] = pk2(bv3.z, bv3.w);
            float am[8] = {av0.x, av0.y, av0.z, av0.w, av1.x, av1.y, av1.z, av1.w};
#pragma unroll
            for (int i = 0; i < 8; i++) {
                unsigned long long ap = pk2(am[i], am[i]);
#pragma unroll
                for (int j = 0; j < 8; j++) ffma2(acc[i][j], ap, bp[j]);
            }
        }
    }

    float* Cbase = g_P + (((size_t)(n * ADAPTERS + k) * BATCH + b0)) * CLASS_DIM + d0;
#pragma unroll
    for (int i = 0; i < 8; i++) {
        int m = m0 + i;
#pragma unroll
        for (int j = 0; j < 4; j++) {
            int d = n0 + j * 4;
            if (d0 + d < CLASS_DIM) {
                float4 o;
                unpk2(acc[i][2 * j], o.x, o.y);
                unpk2(acc[i][2 * j + 1], o.z, o.w);
                *reinterpret_cast<float4*>(Cbase + (size_t)m * CLASS_DIM + d) = o;
            }
        }
    }
}

// ---------------------------------------------------------------------------
// Kernel 2: dynamic routing per (n, b). Logits are constant over d, so they
// collapse to 40-vectors. 3 iterations, final vote written to g_V.
// ---------------------------------------------------------------------------
__global__ __launch_bounds__(256) void k_route(const int* __restrict__ tptr,
                                               const float* __restrict__ tsv) {
    __shared__ float Ps[ADAPTERS][CLASS_DIM];
    __shared__ float tsvv[ADAPTERS], maskv[ADAPTERS];
    __shared__ float l[ADAPTERS], probs[ADAPTERS], leff[ADAPTERS];
    __shared__ float vote[CLASS_DIM], outv[CLASS_DIM];
    __shared__ float coef_s;

    int b = blockIdx.x, n = blockIdx.y;
    int tid = threadIdx.x;
    int t = *tptr;

    const float* Pb = g_P + ((size_t)(n * ADAPTERS) * BATCH + b) * CLASS_DIM;
    for (int idx = tid; idx < ADAPTERS * CLASS_DIM; idx += 256) {
        int k = idx / CLASS_DIM, d = idx - k * CLASS_DIM;
        Ps[k][d] = Pb[(size_t)k * BATCH * CLASS_DIM + d];
    }
    if (tid < ADAPTERS) {
        float tv = tsv[t * ADAPTERS + tid];
        tsvv[tid] = tv;
        maskv[tid] = (tv == 0.f) ? -10000.f : 0.f;
        l[tid] = 0.f;
    }
    __syncthreads();

    for (int it = 0; it < 3; it++) {
        if (tid < ADAPTERS) leff[tid] = l[tid] * tsvv[tid] + maskv[tid];
        __syncthreads();
        if (tid == 0) {
            float mx = leff[0];
            for (int kk = 1; kk < ADAPTERS; kk++) mx = fmaxf(mx, leff[kk]);
            float sm = 0.f;
            for (int kk = 0; kk < ADAPTERS; kk++) {
                float e = expf(leff[kk] - mx);
                probs[kk] = e;
                sm += e;
            }
            float inv = 1.f / sm;
            for (int kk = 0; kk < ADAPTERS; kk++) probs[kk] *= inv;
        }
        __syncthreads();
        if (tid < CLASS_DIM) {
            float v = 0.f;
#pragma unroll 8
            for (int kk = 0; kk < ADAPTERS; kk++) v += probs[kk] * Ps[kk][tid];
            vote[tid] = v;
        }
        __syncthreads();
        if (it == 2) break;

        // squash coefficient: sqrt(sq)/(1+sq)
        if (tid < 32) {
            float p = 0.f;
            for (int d = tid; d < CLASS_DIM; d += 32) {
                float v = vote[d];
                p += v * v;
            }
            for (int o = 16; o > 0; o >>= 1) p += __shfl_down_sync(0xffffffff, p, o);
            if (tid == 0) {
                float sq = p;
                coef_s = sqrtf(sq) / (1.f + sq);
            }
        }
        __syncthreads();
        if (tid < CLASS_DIM) outv[tid] = vote[tid] * coef_s;
        __syncthreads();

        // agreement a[k] = dot(Ps[k], out) -> l[k] += a[k]
        int w = tid >> 5, lane = tid & 31;
        for (int kk = w; kk < ADAPTERS; kk += 8) {
            float p = 0.f;
            for (int d = lane; d < CLASS_DIM; d += 32) p += Ps[kk][d] * outv[d];
            for (int o = 16; o > 0; o >>= 1) p += __shfl_down_sync(0xffffffff, p, o);
            if (lane == 0) l[kk] += p;
        }
        __syncthreads();
    }

    if (tid < CLASS_DIM) g_V[((size_t)n * BATCH + b) * CLASS_DIM + tid] = vote[tid];
}

// ---------------------------------------------------------------------------
// Kernel 3: expansion, v3. Register-resident gated coefficients; thread tid
// owns j = tid*4..tid*4+3, loops over 25 d2 rows. Streaming stores (__stcs)
// since the output is never re-read. Grid (BATCH, 8) for latency hiding.
// ---------------------------------------------------------------------------
#define EXP_SPLIT 8
#define EXP_ROWS (CLASS_DIM / EXP_SPLIT)  // 25

__global__ __launch_bounds__(192) void k_expand(const int* __restrict__ tptr,
                                                const float* __restrict__ s_ptr,
                                                const float* __restrict__ W,
                                                const float* __restrict__ bvec,
                                                const float* __restrict__ el,
                                                float* __restrict__ out) {
    __shared__ float h[CLASS_DIM * CAPS];   // 600

    int b2 = blockIdx.x;
    int d2_0 = blockIdx.y * EXP_ROWS;
    int tid = threadIdx.x;
    int t = *tptr;
    float s = s_ptr[0];

    for (int idx = tid; idx < CLASS_DIM * CAPS; idx += 192)
        h[idx] = g_V[(size_t)b2 * (CLASS_DIM * CAPS) + idx];

    int j = tid * 4;
    float4 e4 = *reinterpret_cast<const float4*>(el + (size_t)t * DHID + j);
    float4 b4 = *reinterpret_cast<const float4*>(bvec + j);
    float g0 = 1.f / (1.f + expf(-s * e4.x));
    float g1 = 1.f / (1.f + expf(-s * e4.y));
    float g2 = 1.f / (1.f + expf(-s * e4.z));
    float g3 = 1.f / (1.f + expf(-s * e4.w));
    // W is [DHID][3]; j*3 = tid*12 is float4-aligned
    float4 w0 = *reinterpret_cast<const float4*>(W + j * 3);
    float4 w1 = *reinterpret_cast<const float4*>(W + j * 3 + 4);
    float4 w2 = *reinterpret_cast<const float4*>(W + j * 3 + 8);
    float4 c0 = make_float4(w0.x * g0, w0.y * g0, w0.z * g0, b4.x * g0);
    float4 c1 = make_float4(w0.w * g1, w1.x * g1, w1.y * g1, b4.y * g1);
    float4 c2 = make_float4(w1.z * g2, w1.w * g2, w2.x * g2, b4.z * g2);
    float4 c3 = make_float4(w2.y * g3, w2.z * g3, w2.w * g3, b4.w * g3);
    __syncthreads();

    float* ob = out + (size_t)b2 * CLASS_DIM * DHID + (size_t)d2_0 * DHID + j;
    const float* hp = h + d2_0 * 3;
#pragma unroll 5
    for (int r = 0; r < EXP_ROWS; r++) {
        float h0 = hp[0], h1 = hp[1], h2 = hp[2];
        hp += 3;
        float4 o;
        o.x = fmaf(h0, c0.x, fmaf(h1, c0.y, fmaf(h2, c0.z, c0.w)));
        o.y = fmaf(h0, c1.x, fmaf(h1, c1.y, fmaf(h2, c1.z, c1.w)));
        o.z = fmaf(h0, c2.x, fmaf(h1, c2.y, fmaf(h2, c2.z, c2.w)));
        o.w = fmaf(h0, c3.x, fmaf(h1, c3.y, fmaf(h2, c3.z, c3.w)));
        __stcs(reinterpret_cast<float4*>(ob), o);
        ob += DHID;
    }
}

// ---------------------------------------------------------------------------
extern "C" void kernel_launch(void* const* d_in, const int* in_sizes, int n_in,
                              void* d_out, int out_size) {
    const int* t = (const int*)d_in[0];
    const float* x = (const float*)d_in[1];
    const float* s = (const float*)d_in[2];
    const float* rw = (const float*)d_in[3];
    const float* W = (const float*)d_in[4];
    const float* bb = (const float*)d_in[5];
    const float* el = (const float*)d_in[6];
    const float* tsv = (const float*)d_in[7];
    float* out = (float*)d_out;

    k_transpose<<<dim3(ADAPTERS, (IN_CH + 31) / 32, BATCH / 32), dim3(32, 8)>>>(x, t);
    k_gemm<<<dim3(BATCH / BM, (CLASS_DIM + BN - 1) / BN, ADAPTERS * CAPS), 128>>>(rw, t);
    k_route<<<dim3(BATCH, CAPS), 256>>>(t, tsv);
    k_expand<<<dim3(BATCH, EXP_SPLIT), 192>>>(t, s, W, bb, el, out);
}

// round 6
// speedup vs baseline: 1.4499x; 1.4499x over previous
#include <cuda_runtime.h>
#include <math.h>

#define ADAPTERS 40
#define CAPS 3
#define CLASS_DIM 200
#define IN_CH 600
#define BATCH 256
#define DHID 768

// Scratch (static device arrays -- no allocation at runtime)
__device__ float g_xT[ADAPTERS * IN_CH * BATCH];          // [k][c][b]
__device__ float g_P[CAPS * ADAPTERS * BATCH * CLASS_DIM]; // [n][k][b][d], zero for k>t
__device__ float g_V[CAPS * BATCH * CLASS_DIM];            // [n][b][d] flat

// ---------------------------------------------------------------------------
// f32x2 packed-FMA helpers (sm_103a FFMA2 path; ptxas won't emit from C++)
// ---------------------------------------------------------------------------
__device__ __forceinline__ unsigned long long pk2(float lo, float hi) {
    unsigned long long r;
    asm("mov.b64 %0, {%1, %2};" : "=l"(r) : "f"(lo), "f"(hi));
    return r;
}
__device__ __forceinline__ void ffma2(unsigned long long& c, unsigned long long a, unsigned long long b) {
    asm("fma.rn.f32x2 %0, %1, %2, %0;" : "+l"(c) : "l"(a), "l"(b));
}
__device__ __forceinline__ void unpk2(unsigned long long v, float& lo, float& hi) {
    asm("mov.b64 {%0, %1}, %2;" : "=f"(lo), "=f"(hi) : "l"(v));
}

// ---------------------------------------------------------------------------
// Kernel 0: transpose x (b,k,c) -> xT (k,c,b); only k<=t slices are consumed
// ---------------------------------------------------------------------------
__global__ void k_transpose(const float* __restrict__ x, const int* __restrict__ tptr) {
    int k = blockIdx.x;
    if (k > *tptr) return;
    __shared__ float tile[32][33];
    int c0 = blockIdx.y * 32;
    int b0 = blockIdx.z * 32;
    int tx = threadIdx.x, ty = threadIdx.y;  // (32, 8)
#pragma unroll
    for (int i = 0; i < 4; i++) {
        int b = b0 + ty + i * 8;
        int c = c0 + tx;
        float v = 0.f;
        if (c < IN_CH) v = x[((size_t)b * ADAPTERS + k) * IN_CH + c];
        tile[ty + i * 8][tx] = v;
    }
    __syncthreads();
#pragma unroll
    for (int i = 0; i < 4; i++) {
        int c = c0 + ty + i * 8;
        int b = b0 + tx;
        if (c < IN_CH) g_xT[((size_t)k * IN_CH + c) * BATCH + b] = tile[tx][ty + i * 8];
    }
}

// ---------------------------------------------------------------------------
// Kernel 1: priors GEMM v4. Per k: C[256 x 600] = A[256x600] @ B[600x600]
// where the 600-wide N dim fuses (n, d) = n*200+d (rw[k] is [3][600][200],
// so cols within one n-region are contiguous; 200%4==0 keeps float4 groups
// inside one region -> per-thread constant (n,d) addressing).
// BM=128, BN=64, BK=8, 128 threads, 8x8 per-thread tile with SPLIT 4+4
// fragments: n in {tn*4..+3} u {32+tn*4..+3} -> conflict-free LDS.128.
// Double-buffered smem, ONE __syncthreads per K-step.
// ---------------------------------------------------------------------------
#define BM 128
#define BN 64
#define BKK 8
#define NT (IN_CH / BKK)   // 75
#define NFUSED (CAPS * CLASS_DIM)  // 600

__global__ __launch_bounds__(128) void k_gemm(const float* __restrict__ rw,
                                              const int* __restrict__ tptr) {
    int k = blockIdx.z;
    if (k > *tptr) return;  // only k<=t contribute (softmax underflow), uniform exit

    int b0 = blockIdx.x * BM;   // 0 or 128
    int g0 = blockIdx.y * BN;   // 0..576

    __shared__ float As[2][BKK][BM];
    __shared__ float Bs[2][BKK][BN];

    int tid = threadIdx.x;
    int tn = tid & 7;        // 0..7
    int tm = tid >> 3;       // 0..15

    // A tile loads (8x128 = 256 float4, 2/thread), STS conflict-free
    int arow = tid >> 5;          // 0..3 (+4 for second)
    int acol = (tid & 31) * 4;    // 0..124
    const float* Aptr = g_xT + ((size_t)k * IN_CH + arow) * BATCH + b0 + acol;

    // B tile load (8x64 = 128 float4, 1/thread)
    int brow = tid >> 4;          // 0..7
    int bcol = (tid & 15) * 4;    // 0..60
    int gb = g0 + bcol;
    bool bvalid = gb < NFUSED;
    int nB = gb / CLASS_DIM;
    int dB = gb - nB * CLASS_DIM;
    const float* Bptr = rw + (((size_t)(k * CAPS + nB)) * IN_CH + brow) * CLASS_DIM + dB;

    unsigned long long acc[8][4];
#pragma unroll
    for (int i = 0; i < 8; i++)
#pragma unroll
        for (int j = 0; j < 4; j++) acc[i][j] = 0ull;

    // Prologue: tile 0
    float4 a0 = *reinterpret_cast<const float4*>(Aptr);
    float4 a1 = *reinterpret_cast<const float4*>(Aptr + 4 * BATCH);
    float4 bbv = make_float4(0.f, 0.f, 0.f, 0.f);
    if (bvalid) bbv = *reinterpret_cast<const float4*>(Bptr);
    Aptr += BKK * BATCH;
    Bptr += BKK * CLASS_DIM;

    *reinterpret_cast<float4*>(&As[0][arow][acol]) = a0;
    *reinterpret_cast<float4*>(&As[0][arow + 4][acol]) = a1;
    *reinterpret_cast<float4*>(&Bs[0][brow][bcol]) = bbv;
    __syncthreads();

    int w = 0;
    for (int ct = 0; ct < NT; ct++) {
        bool more = (ct + 1 < NT);
        if (more) {
            a0 = *reinterpret_cast<const float4*>(Aptr);
            a1 = *reinterpret_cast<const float4*>(Aptr + 4 * BATCH);
            if (bvalid) bbv = *reinterpret_cast<const float4*>(Bptr);
            Aptr += BKK * BATCH;
            Bptr += BKK * CLASS_DIM;
        }

#pragma unroll
        for (int kk = 0; kk < BKK; kk++) {
            const float4 av0 = *reinterpret_cast<const float4*>(&As[w][kk][tm * 4]);
            const float4 av1 = *reinterpret_cast<const float4*>(&As[w][kk][64 + tm * 4]);
            const ulonglong2 q0 = *reinterpret_cast<const ulonglong2*>(&Bs[w][kk][tn * 4]);
            const ulonglong2 q1 = *reinterpret_cast<const ulonglong2*>(&Bs[w][kk][32 + tn * 4]);
            float am[8] = {av0.x, av0.y, av0.z, av0.w, av1.x, av1.y, av1.z, av1.w};
#pragma unroll
            for (int i = 0; i < 8; i++) {
                unsigned long long ap = pk2(am[i], am[i]);
                ffma2(acc[i][0], ap, q0.x);
                ffma2(acc[i][1], ap, q0.y);
                ffma2(acc[i][2], ap, q1.x);
                ffma2(acc[i][3], ap, q1.y);
            }
        }

        if (more) {
            int nw = w ^ 1;
            *reinterpret_cast<float4*>(&As[nw][arow][acol]) = a0;
            *reinterpret_cast<float4*>(&As[nw][arow + 4][acol]) = a1;
            *reinterpret_cast<float4*>(&Bs[nw][brow][bcol]) = bbv;
            __syncthreads();
            w = nw;
        }
    }

    // Epilogue: two float4 column groups per thread, each inside one n-region
    int gc0 = g0 + tn * 4;
    int gc1 = g0 + 32 + tn * 4;
    if (gc0 < NFUSED) {
        int n = gc0 / CLASS_DIM, d = gc0 - n * CLASS_DIM;
        float* p = g_P + ((size_t)(n * ADAPTERS + k) * BATCH) * CLASS_DIM + d;
#pragma unroll
        for (int i = 0; i < 8; i++) {
            int m = b0 + tm * 4 + (i < 4 ? i : 60 + i);  // second half offset +64
            float4 o;
            unpk2(acc[i][0], o.x, o.y);
            unpk2(acc[i][1], o.z, o.w);
            *reinterpret_cast<float4*>(p + (size_t)m * CLASS_DIM) = o;
        }
    }
    if (gc1 < NFUSED) {
        int n = gc1 / CLASS_DIM, d = gc1 - n * CLASS_DIM;
        float* p = g_P + ((size_t)(n * ADAPTERS + k) * BATCH) * CLASS_DIM + d;
#pragma unroll
        for (int i = 0; i < 8; i++) {
            int m = b0 + tm * 4 + (i < 4 ? i : 60 + i);
            float4 o;
            unpk2(acc[i][2], o.x, o.y);
            unpk2(acc[i][3], o.z, o.w);
            *reinterpret_cast<float4*>(p + (size_t)m * CLASS_DIM) = o;
        }
    }
}

// ---------------------------------------------------------------------------
// Kernel 2: dynamic routing per (n, b). Logits are constant over d, so they
// collapse to 40-vectors. 3 iterations, final vote written to g_V.
// ---------------------------------------------------------------------------
__global__ __launch_bounds__(256) void k_route(const int* __restrict__ tptr,
                                               const float* __restrict__ tsv) {
    __shared__ float Ps[ADAPTERS][CLASS_DIM];
    __shared__ float tsvv[ADAPTERS], maskv[ADAPTERS];
    __shared__ float l[ADAPTERS], probs[ADAPTERS], leff[ADAPTERS];
    __shared__ float vote[CLASS_DIM], outv[CLASS_DIM];
    __shared__ float coef_s;

    int b = blockIdx.x, n = blockIdx.y;
    int tid = threadIdx.x;
    int t = *tptr;

    const float* Pb = g_P + ((size_t)(n * ADAPTERS) * BATCH + b) * CLASS_DIM;
    for (int idx = tid; idx < ADAPTERS * CLASS_DIM; idx += 256) {
        int k = idx / CLASS_DIM, d = idx - k * CLASS_DIM;
        Ps[k][d] = Pb[(size_t)k * BATCH * CLASS_DIM + d];
    }
    if (tid < ADAPTERS) {
        float tv = tsv[t * ADAPTERS + tid];
        tsvv[tid] = tv;
        maskv[tid] = (tv == 0.f) ? -10000.f : 0.f;
        l[tid] = 0.f;
    }
    __syncthreads();

    for (int it = 0; it < 3; it++) {
        if (tid < ADAPTERS) leff[tid] = l[tid] * tsvv[tid] + maskv[tid];
        __syncthreads();
        if (tid == 0) {
            float mx = leff[0];
            for (int kk = 1; kk < ADAPTERS; kk++) mx = fmaxf(mx, leff[kk]);
            float sm = 0.f;
            for (int kk = 0; kk < ADAPTERS; kk++) {
                float e = expf(leff[kk] - mx);
                probs[kk] = e;
                sm += e;
            }
            float inv = 1.f / sm;
            for (int kk = 0; kk < ADAPTERS; kk++) probs[kk] *= inv;
        }
        __syncthreads();
        if (tid < CLASS_DIM) {
            float v = 0.f;
#pragma unroll 8
            for (int kk = 0; kk < ADAPTERS; kk++) v += probs[kk] * Ps[kk][tid];
            vote[tid] = v;
        }
        __syncthreads();
        if (it == 2) break;

        // squash coefficient: sqrt(sq)/(1+sq)
        if (tid < 32) {
            float p = 0.f;
            for (int d = tid; d < CLASS_DIM; d += 32) {
                float v = vote[d];
                p += v * v;
            }
            for (int o = 16; o > 0; o >>= 1) p += __shfl_down_sync(0xffffffff, p, o);
            if (tid == 0) {
                float sq = p;
                coef_s = sqrtf(sq) / (1.f + sq);
            }
        }
        __syncthreads();
        if (tid < CLASS_DIM) outv[tid] = vote[tid] * coef_s;
        __syncthreads();

        // agreement a[k] = dot(Ps[k], out) -> l[k] += a[k]
        int w = tid >> 5, lane = tid & 31;
        for (int kk = w; kk < ADAPTERS; kk += 8) {
            float p = 0.f;
            for (int d = lane; d < CLASS_DIM; d += 32) p += Ps[kk][d] * outv[d];
            for (int o = 16; o > 0; o >>= 1) p += __shfl_down_sync(0xffffffff, p, o);
            if (lane == 0) l[kk] += p;
        }
        __syncthreads();
    }

    if (tid < CLASS_DIM) g_V[((size_t)n * BATCH + b) * CLASS_DIM + tid] = vote[tid];
}

// ---------------------------------------------------------------------------
// Kernel 3: expansion. Register-resident gated coefficients; thread tid owns
// j = tid*4..tid*4+3, loops over 25 d2 rows. Streaming stores (__stcs).
// ---------------------------------------------------------------------------
#define EXP_SPLIT 8
#define EXP_ROWS (CLASS_DIM / EXP_SPLIT)  // 25

__global__ __launch_bounds__(192) void k_expand(const int* __restrict__ tptr,
                                                const float* __restrict__ s_ptr,
                                                const float* __restrict__ W,
                                                const float* __restrict__ bvec,
                                                const float* __restrict__ el,
                                                float* __restrict__ out) {
    __shared__ float h[CLASS_DIM * CAPS];   // 600

    int b2 = blockIdx.x;
    int d2_0 = blockIdx.y * EXP_ROWS;
    int tid = threadIdx.x;
    int t = *tptr;
    float s = s_ptr[0];

    for (int idx = tid; idx < CLASS_DIM * CAPS; idx += 192)
        h[idx] = g_V[(size_t)b2 * (CLASS_DIM * CAPS) + idx];

    int j = tid * 4;
    float4 e4 = *reinterpret_cast<const float4*>(el + (size_t)t * DHID + j);
    float4 b4 = *reinterpret_cast<const float4*>(bvec + j);
    float g0 = 1.f / (1.f + expf(-s * e4.x));
    float g1 = 1.f / (1.f + expf(-s * e4.y));
    float g2 = 1.f / (1.f + expf(-s * e4.z));
    float g3 = 1.f / (1.f + expf(-s * e4.w));
    // W is [DHID][3]; j*3 = tid*12 is float4-aligned
    float4 w0 = *reinterpret_cast<const float4*>(W + j * 3);
    float4 w1 = *reinterpret_cast<const float4*>(W + j * 3 + 4);
    float4 w2 = *reinterpret_cast<const float4*>(W + j * 3 + 8);
    float4 c0 = make_float4(w0.x * g0, w0.y * g0, w0.z * g0, b4.x * g0);
    float4 c1 = make_float4(w0.w * g1, w1.x * g1, w1.y * g1, b4.y * g1);
    float4 c2 = make_float4(w1.z * g2, w1.w * g2, w2.x * g2, b4.z * g2);
    float4 c3 = make_float4(w2.y * g3, w2.z * g3, w2.w * g3, b4.w * g3);
    __syncthreads();

    float* ob = out + (size_t)b2 * CLASS_DIM * DHID + (size_t)d2_0 * DHID + j;
    const float* hp = h + d2_0 * 3;
#pragma unroll 5
    for (int r = 0; r < EXP_ROWS; r++) {
        float h0 = hp[0], h1 = hp[1], h2 = hp[2];
        hp += 3;
        float4 o;
        o.x = fmaf(h0, c0.x, fmaf(h1, c0.y, fmaf(h2, c0.z, c0.w)));
        o.y = fmaf(h0, c1.x, fmaf(h1, c1.y, fmaf(h2, c1.z, c1.w)));
        o.z = fmaf(h0, c2.x, fmaf(h1, c2.y, fmaf(h2, c2.z, c2.w)));
        o.w = fmaf(h0, c3.x, fmaf(h1, c3.y, fmaf(h2, c3.z, c3.w)));
        __stcs(reinterpret_cast<float4*>(ob), o);
        ob += DHID;
    }
}

// ---------------------------------------------------------------------------
extern "C" void kernel_launch(void* const* d_in, const int* in_sizes, int n_in,
                              void* d_out, int out_size) {
    const int* t = (const int*)d_in[0];
    const float* x = (const float*)d_in[1];
    const float* s = (const float*)d_in[2];
    const float* rw = (const float*)d_in[3];
    const float* W = (const float*)d_in[4];
    const float* bb = (const float*)d_in[5];
    const float* el = (const float*)d_in[6];
    const float* tsv = (const float*)d_in[7];
    float* out = (float*)d_out;

    k_transpose<<<dim3(ADAPTERS, (IN_CH + 31) / 32, BATCH / 32), dim3(32, 8)>>>(x, t);
    k_gemm<<<dim3(BATCH / BM, (NFUSED + BN - 1) / BN, ADAPTERS), 128>>>(rw, t);
    k_route<<<dim3(BATCH, CAPS), 256>>>(t, tsv);
    k_expand<<<dim3(BATCH, EXP_SPLIT), 192>>>(t, s, W, bb, el, out);
}